// round 4
// baseline (speedup 1.0000x reference)
#include <cuda_runtime.h>

// WarpImage R4: smem-staged bilinear warp (R3 + border-tap fix).
// image [32,1024,2048] f32, flow [2,1024,2048] f32 -> out [32,1024,2048] f32.
// 64x16 pixel tile per block; per channel the (82x33) clamped image window is
// staged into smem (double-buffered, prefetch c+1 while gathering c).
// Border semantics: taps use independently clamped u0/u1/v0/v1 (du/dv step
// offsets), out-of-image taps zeroed via weights — exact reference match.

#define CC 32
#define HH 1024
#define WW 2048
#define HWSZ (HH * WW)

#define TW 64           // tile width (pixels)
#define TH 16           // tile height
#define HALO 8
#define SW 82           // staged cols: TW + 2*HALO + 2
#define SROWS 33        // staged rows: TH + 2*HALO + 1
#define SSTRIDE 97      // padded stride (mod 32 == 1)
#define SELEMS (SW * SROWS)   // 2706
#define NTHREADS 512
#define FULL_ITERS (SELEMS / NTHREADS)        // 5
#define TAIL (SELEMS - FULL_ITERS * NTHREADS) // 146

struct Px {
    float w00, w10, w01, w11;
    int a;     // smem offset of (v0c,u0c) tap
    int du;    // 0 or 1        (= clamp(u0+1)-clamp(u0))
    int dv;    // 0 or SSTRIDE  (= (clamp(v0+1)-clamp(v0)) * SSTRIDE)
    int idx;   // output pixel offset within one channel plane
};

__device__ __forceinline__ Px setup_pixel(const float* __restrict__ flow,
                                          int w, int h, int w0, int h0)
{
    Px p;
    p.idx = h * WW + w;
    float u = (float)w + __ldg(flow + p.idx);
    float v = (float)h + __ldg(flow + HWSZ + p.idx);

    float u0f = floorf(u);
    float v0f = floorf(v);
    float wu = u - u0f;
    float wv = v - v0f;

    int u0 = (int)u0f;
    int v0 = (int)v0f;

    bool vu0 = (u0 >= 0) && (u0 <= WW - 1);
    bool vu1 = (u0 + 1 >= 0) && (u0 + 1 <= WW - 1);
    bool vv0 = (v0 >= 0) && (v0 <= HH - 1);
    bool vv1 = (v0 + 1 >= 0) && (v0 + 1 <= HH - 1);

    p.w00 = (1.0f - wu) * (1.0f - wv); if (!(vu0 && vv0)) p.w00 = 0.0f;
    p.w10 = wu * (1.0f - wv);          if (!(vu1 && vv0)) p.w10 = 0.0f;
    p.w01 = (1.0f - wu) * wv;          if (!(vu0 && vv1)) p.w01 = 0.0f;
    p.w11 = wu * wv;                   if (!(vu1 && vv1)) p.w11 = 0.0f;

    int u0c = min(max(u0, 0), WW - 1);
    int v0c = min(max(v0, 0), HH - 1);

    // step offsets: clamp(x0+1) - clamp(x0)
    p.du = ((u0 >= 0) && (u0 <= WW - 2)) ? 1 : 0;
    p.dv = ((v0 >= 0) && (v0 <= HH - 2)) ? SSTRIDE : 0;

    // local staged coords; clamp for memory safety (all real taps in range)
    int lu = min(max(u0c - (w0 - HALO), 0), SW - 2);
    int lv = min(max(v0c - (h0 - HALO), 0), SROWS - 2);
    p.a = lv * SSTRIDE + lu;
    return p;
}

__global__ __launch_bounds__(NTHREADS, 2) void warp_image_kernel(
    const float* __restrict__ image,
    const float* __restrict__ flow,
    float* __restrict__ out)
{
    __shared__ float buf[2][SSTRIDE * SROWS];

    const int tid = threadIdx.y * TW + threadIdx.x;
    const int w0 = blockIdx.x * TW;
    const int h0 = blockIdx.y * TH;

    // ---- channel-invariant staging offsets ----
    int g_off[FULL_ITERS + 1];
    int s_off[FULL_ITERS + 1];
    #pragma unroll
    for (int j = 0; j <= FULL_ITERS; j++) {
        int k = tid + j * NTHREADS;
        if (k >= SELEMS) k = SELEMS - 1;   // dummy (never stored for inactive tail)
        int r = k / SW;
        int col = k - r * SW;
        int gv = min(max(h0 - HALO + r, 0), HH - 1);
        int gu = min(max(w0 - HALO + col, 0), WW - 1);
        g_off[j] = gv * WW + gu;
        s_off[j] = r * SSTRIDE + col;
    }

    // ---- per-pixel setup: 2 pixels per thread ----
    const int w = w0 + threadIdx.x;
    Px pa = setup_pixel(flow, w, h0 + threadIdx.y, w0, h0);
    Px pb = setup_pixel(flow, w, h0 + threadIdx.y + 8, w0, h0);

    // ---- prologue: stage channel 0 ----
    {
        float st[FULL_ITERS + 1];
        #pragma unroll
        for (int j = 0; j < FULL_ITERS; j++) st[j] = __ldg(image + g_off[j]);
        if (tid < TAIL) st[FULL_ITERS] = __ldg(image + g_off[FULL_ITERS]);
        #pragma unroll
        for (int j = 0; j < FULL_ITERS; j++) buf[0][s_off[j]] = st[j];
        if (tid < TAIL) buf[0][s_off[FULL_ITERS]] = st[FULL_ITERS];
    }
    __syncthreads();

    const float* imgc = image;
    float* outc = out;

    #pragma unroll 1
    for (int c = 0; c < CC; c++) {
        // prefetch channel c+1 into regs before gathering channel c
        float pf[FULL_ITERS + 1];
        if (c < CC - 1) {
            const float* imgn = imgc + HWSZ;
            #pragma unroll
            for (int j = 0; j < FULL_ITERS; j++) pf[j] = __ldg(imgn + g_off[j]);
            if (tid < TAIL) pf[FULL_ITERS] = __ldg(imgn + g_off[FULL_ITERS]);
        }

        // gather channel c from smem
        const float* S = buf[c & 1];
        float ga = pa.w00 * S[pa.a]
                 + pa.w10 * S[pa.a + pa.du]
                 + pa.w01 * S[pa.a + pa.dv]
                 + pa.w11 * S[pa.a + pa.dv + pa.du];
        float gb = pb.w00 * S[pb.a]
                 + pb.w10 * S[pb.a + pb.du]
                 + pb.w01 * S[pb.a + pb.dv]
                 + pb.w11 * S[pb.a + pb.dv + pb.du];
        outc[pa.idx] = ga;
        outc[pb.idx] = gb;

        // commit prefetched channel c+1 into the other buffer
        if (c < CC - 1) {
            float* D = buf[(c + 1) & 1];
            #pragma unroll
            for (int j = 0; j < FULL_ITERS; j++) D[s_off[j]] = pf[j];
            if (tid < TAIL) D[s_off[FULL_ITERS]] = pf[FULL_ITERS];
        }
        __syncthreads();

        imgc += HWSZ;
        outc += HWSZ;
    }
}

extern "C" void kernel_launch(void* const* d_in, const int* in_sizes, int n_in,
                              void* d_out, int out_size)
{
    const float* image = (const float*)d_in[0];
    const float* flow  = (const float*)d_in[1];
    float* out = (float*)d_out;

    dim3 block(TW, NTHREADS / TW);     // (64, 8)
    dim3 grid(WW / TW, HH / TH);       // (32, 64)
    warp_image_kernel<<<grid, block>>>(image, flow, out);
}

// round 5
// speedup vs baseline: 1.7348x; 1.7348x over previous
#include <cuda_runtime.h>

// WarpImage R5: direct-gather bilinear warp (R2 structure) with 32x32 pixel
// tiles (4 px/thread vertically) to amortize the flow-halo L1 fill traffic,
// which R2's profile showed was ~40% of L1 wavefronts (1.4GB L2 reads vs
// 0.52GB DRAM).

#define CC 32
#define HH 1024
#define WW 2048
#define HWSZ (HH * WW)

#define PXY 4            // pixels per thread (vertical)
#define TILE_H (8 * PXY) // 32

struct Px {
    float w00, w10, w01, w11;
    int o00, o10, o01, o11;  // clamped global offsets of the 4 taps
    int idx;                 // output offset within one channel plane
};

__device__ __forceinline__ Px setup_pixel(const float* __restrict__ flow,
                                          int w, int h)
{
    Px p;
    p.idx = h * WW + w;
    float u = (float)w + __ldg(flow + p.idx);
    float v = (float)h + __ldg(flow + HWSZ + p.idx);

    float u0f = floorf(u);
    float v0f = floorf(v);
    float wu = u - u0f;
    float wv = v - v0f;

    int u0 = (int)u0f;
    int v0 = (int)v0f;
    int u1 = u0 + 1;
    int v1 = v0 + 1;

    bool vu0 = (u0 >= 0) && (u0 <= WW - 1);
    bool vu1 = (u1 >= 0) && (u1 <= WW - 1);
    bool vv0 = (v0 >= 0) && (v0 <= HH - 1);
    bool vv1 = (v1 >= 0) && (v1 <= HH - 1);

    p.w00 = (1.0f - wu) * (1.0f - wv); if (!(vu0 && vv0)) p.w00 = 0.0f;
    p.w10 = wu * (1.0f - wv);          if (!(vu1 && vv0)) p.w10 = 0.0f;
    p.w01 = (1.0f - wu) * wv;          if (!(vu0 && vv1)) p.w01 = 0.0f;
    p.w11 = wu * wv;                   if (!(vu1 && vv1)) p.w11 = 0.0f;

    int u0c = min(max(u0, 0), WW - 1);
    int u1c = min(max(u1, 0), WW - 1);
    int v0c = min(max(v0, 0), HH - 1);
    int v1c = min(max(v1, 0), HH - 1);

    p.o00 = v0c * WW + u0c;
    p.o10 = v0c * WW + u1c;
    p.o01 = v1c * WW + u0c;
    p.o11 = v1c * WW + u1c;
    return p;
}

__global__ __launch_bounds__(256, 4) void warp_image_kernel(
    const float* __restrict__ image,
    const float* __restrict__ flow,
    float* __restrict__ out)
{
    const int w = blockIdx.x * 32 + threadIdx.x;
    const int h0 = blockIdx.y * TILE_H + threadIdx.y;

    Px px[PXY];
    #pragma unroll
    for (int k = 0; k < PXY; k++)
        px[k] = setup_pixel(flow, w, h0 + 8 * k);

    const float* imgc = image;
    float* outc = out;

    #pragma unroll 1
    for (int c = 0; c < CC; c++) {
        float g[PXY];
        // issue all 16 gathers before consuming (deep MLP)
        float t00[PXY], t10[PXY], t01[PXY], t11[PXY];
        #pragma unroll
        for (int k = 0; k < PXY; k++) {
            t00[k] = __ldg(imgc + px[k].o00);
            t10[k] = __ldg(imgc + px[k].o10);
            t01[k] = __ldg(imgc + px[k].o01);
            t11[k] = __ldg(imgc + px[k].o11);
        }
        #pragma unroll
        for (int k = 0; k < PXY; k++) {
            g[k] = px[k].w00 * t00[k]
                 + px[k].w10 * t10[k]
                 + px[k].w01 * t01[k]
                 + px[k].w11 * t11[k];
            outc[px[k].idx] = g[k];
        }
        imgc += HWSZ;
        outc += HWSZ;
    }
}

extern "C" void kernel_launch(void* const* d_in, const int* in_sizes, int n_in,
                              void* d_out, int out_size)
{
    const float* image = (const float*)d_in[0];
    const float* flow  = (const float*)d_in[1];
    float* out = (float*)d_out;

    // maximize L1 (no smem used) — harmless if the driver ignores it
    static bool carveout_set = false;
    // NOTE: no static guards allowed for *work*; attribute set is idempotent
    // and deterministic, call it every time to stay within the rules.
    (void)carveout_set;
    cudaFuncSetAttribute(warp_image_kernel,
                         cudaFuncAttributePreferredSharedMemoryCarveout, 0);

    dim3 block(32, 8);
    dim3 grid(WW / 32, HH / TILE_H);   // (64, 32)
    warp_image_kernel<<<grid, block>>>(image, flow, out);
}